// round 15
// baseline (speedup 1.0000x reference)
#include <cuda_runtime.h>

typedef unsigned long long ull;

// image-paired ping-pong buffers: P[pair][ch][row][col] = float2(x[img p], x[img p+8])
__device__ float2 g_p0[8u * 3u * 1024u * 1024u];
__device__ float2 g_p1[8u * 3u * 1024u * 1024u];
// pre-packed (w,w) f32x2 weights, layout [ci][kx][s=co*5+ky] padded to 16
__device__ ull    g_wpack[240];

__device__ __forceinline__ ull pack2(float lo, float hi) {
    ull r;
    asm("mov.b64 %0, {%1, %2};" : "=l"(r) : "f"(lo), "f"(hi));
    return r;
}
__device__ __forceinline__ float2 unpack2(ull v) {
    float2 r;
    asm("mov.b64 {%0, %1}, %2;" : "=f"(r.x), "=f"(r.y) : "l"(v));
    return r;
}
__device__ __forceinline__ void fma2(ull& d, ull a, ull b) {
    asm("fma.rn.f32x2 %0, %1, %2, %0;" : "+l"(d) : "l"(a), "l"(b));
}
__device__ __forceinline__ void cp16(void* dst_smem, const void* src_gmem) {
    unsigned d = (unsigned)__cvta_generic_to_shared(dst_smem);
    asm volatile("cp.async.cg.shared.global [%0], [%1], 16;" :: "r"(d), "l"(src_gmem));
}
__device__ __forceinline__ void cp_commit() {
    asm volatile("cp.async.commit_group;");
}
__device__ __forceinline__ void cp_wait_all() {
    asm volatile("cp.async.wait_group 0;" ::: "memory");
}

// prep: broadcast-pack weights once; W is OIHW [co][ci][ky][kx] = [3][3][5][5]
__global__ void pack_w(const float* __restrict__ W) {
    int i = threadIdx.x;
    if (i >= 240) return;
    int ci = i / 80;
    int r  = i - ci * 80;
    int kx = r / 16;
    int s  = r - kx * 16;
    float w = 0.0f;
    if (s < 15) {
        int co = s / 5;
        int ky = s - co * 5;
        w = W[co * 75 + ci * 25 + ky * 5 + kx];
    }
    g_wpack[i] = pack2(w, w);
}

__device__ __forceinline__ void fma8(ull* accrow, const ull* base, ull w) {
    #pragma unroll
    for (int p = 0; p < 8; ++p)
        fma2(accrow[p], base[p], w);
}
__device__ __forceinline__ void load_window(ull* rv, const float2* colbase, int kx) {
    #pragma unroll
    for (int p = 0; p < 12; ++p)
        rv[p] = *reinterpret_cast<const ull*>(colbase + p * 132 + kx);
}
// tile-2 window: rows 0..3 from main[8..11], rows 4..11 from aux[0..7] (compile-time)
__device__ __forceinline__ void load_window2(ull* rv, const float2* cbM,
                                             const float2* cbA, int kx) {
    #pragma unroll
    for (int p = 0; p < 4; ++p)
        rv[p] = *reinterpret_cast<const ull*>(cbM + p * 132 + kx);
    #pragma unroll
    for (int p = 4; p < 12; ++p)
        rv[p] = *reinterpret_cast<const ull*>(cbA + (p - 4) * 132 + kx);
}
// one (ci,kx) chunk: 8 weight LDS.128 pairs + 120 FFMA2 (R5/R6/R12-proven order)
__device__ __forceinline__ void fchunk(ull (*acc)[8], const ull* rv, const ull* wrow) {
    const ulonglong2* wv = reinterpret_cast<const ulonglong2*>(wrow);
    #pragma unroll
    for (int j = 0; j < 7; ++j) {
        ulonglong2 q = wv[j];
        const int s0 = 2 * j;
        const int s1 = 2 * j + 1;
        fma8(acc[s0 / 5], rv + (s0 % 5), q.x);
        fma8(acc[s1 / 5], rv + (s1 % 5), q.y);
    }
    fma8(acc[2], rv + 4, wrow[14]);   // s=14 -> co=2, ky=4
}

// ===========================================================================
// R12 kernel (unchanged): used for step 0 (normal->paired) and step 9 (->out)
// ===========================================================================
template <int INP, int OUTP>
__global__ void __launch_bounds__(128, 4) ca_step(const float*  __restrict__ srcN,
                                                  const float2* __restrict__ srcP,
                                                  float*        __restrict__ dstN,
                                                  float2*       __restrict__ dstP)
{
    __shared__ __align__(16) float2 smx[3][12][132];
    __shared__ __align__(16) ull    wS[240];

    const int tid  = threadIdx.x;
    const int xb   = blockIdx.x * 128;
    const int rb   = blockIdx.y * 8;
    const int pair = blockIdx.z;

    if (tid < 120) {
        wS[tid]       = g_wpack[tid];
        wS[tid + 120] = g_wpack[tid + 120];
    }

    if (INP) {
        #pragma unroll
        for (int ch = 0; ch < 3; ++ch) {
            const float2* pbase = srcP + (((size_t)(pair * 3 + ch)) << 20);
            #pragma unroll
            for (int k = 0; k < 6; ++k) {
                int j   = k * 128 + tid;
                int row = j >> 6;
                int c2  = j & 63;
                const float4* sp = reinterpret_cast<const float4*>(
                    pbase + (((rb + row - 2) & 1023) << 10) + xb + 2 * c2);
                *reinterpret_cast<float4*>(&smx[ch][row][2 + 2 * c2]) = *sp;
            }
        }
        if (tid < 72) {
            int ch   = tid / 24;
            int rem  = tid - ch * 24;
            int row  = rem >> 1;
            int side = rem & 1;
            int gcol = side ? ((xb + 128) & 1023) : ((xb - 2) & 1023);
            int sidx = side ? 130 : 0;
            const float2* pbase = srcP + (((size_t)(pair * 3 + ch)) << 20);
            const float4* sp = reinterpret_cast<const float4*>(
                pbase + (((rb + row - 2) & 1023) << 10) + gcol);
            *reinterpret_cast<float4*>(&smx[ch][row][sidx]) = *sp;
        }
    } else {
        #pragma unroll
        for (int ch = 0; ch < 3; ++ch) {
            const float* baseA = srcN + (((size_t)(pair * 3 + ch)) << 20);
            const float* baseB = baseA + (((size_t)24) << 20);
            #pragma unroll
            for (int k = 0; k < 3; ++k) {
                int j   = k * 128 + tid;
                int row = j >> 5;
                int g   = j & 31;
                int off = (((rb + row - 2) & 1023) << 10) + xb + 4 * g;
                float4 a = *reinterpret_cast<const float4*>(baseA + off);
                float4 b = *reinterpret_cast<const float4*>(baseB + off);
                float4* s = reinterpret_cast<float4*>(&smx[ch][row][2 + 4 * g]);
                s[0] = make_float4(a.x, b.x, a.y, b.y);
                s[1] = make_float4(a.z, b.z, a.w, b.w);
            }
        }
        if (tid < 72) {
            int ch   = tid / 24;
            int rem  = tid - ch * 24;
            int row  = rem >> 1;
            int side = rem & 1;
            int gcol = side ? ((xb + 128) & 1023) : ((xb - 2) & 1023);
            int sidx = side ? 130 : 0;
            const float* baseA = srcN + (((size_t)(pair * 3 + ch)) << 20);
            const float* baseB = baseA + (((size_t)24) << 20);
            int off = (((rb + row - 2) & 1023) << 10) + gcol;
            float2 a = *reinterpret_cast<const float2*>(baseA + off);
            float2 b = *reinterpret_cast<const float2*>(baseB + off);
            *reinterpret_cast<float4*>(&smx[ch][row][sidx]) =
                make_float4(a.x, b.x, a.y, b.y);
        }
    }
    __syncthreads();

    ull acc[3][8];
    #pragma unroll
    for (int co = 0; co < 3; ++co)
        #pragma unroll
        for (int p = 0; p < 8; ++p)
            acc[co][p] = 0ull;

    const float2* cb0 = &smx[0][0][tid];
    const float2* cb1 = &smx[1][0][tid];
    const float2* cb2 = &smx[2][0][tid];

    ull rvA[12], rvB[12];
    load_window(rvA, cb0, 0);
    load_window(rvB, cb0, 1);  fchunk(acc, rvA, &wS[0 * 80 + 0 * 16]);
    load_window(rvA, cb0, 2);  fchunk(acc, rvB, &wS[0 * 80 + 1 * 16]);
    load_window(rvB, cb0, 3);  fchunk(acc, rvA, &wS[0 * 80 + 2 * 16]);
    load_window(rvA, cb0, 4);  fchunk(acc, rvB, &wS[0 * 80 + 3 * 16]);
    load_window(rvB, cb1, 0);  fchunk(acc, rvA, &wS[0 * 80 + 4 * 16]);
    load_window(rvA, cb1, 1);  fchunk(acc, rvB, &wS[1 * 80 + 0 * 16]);
    load_window(rvB, cb1, 2);  fchunk(acc, rvA, &wS[1 * 80 + 1 * 16]);
    load_window(rvA, cb1, 3);  fchunk(acc, rvB, &wS[1 * 80 + 2 * 16]);
    load_window(rvB, cb1, 4);  fchunk(acc, rvA, &wS[1 * 80 + 3 * 16]);
    load_window(rvA, cb2, 0);  fchunk(acc, rvB, &wS[1 * 80 + 4 * 16]);
    load_window(rvB, cb2, 1);  fchunk(acc, rvA, &wS[2 * 80 + 0 * 16]);
    load_window(rvA, cb2, 2);  fchunk(acc, rvB, &wS[2 * 80 + 1 * 16]);
    load_window(rvB, cb2, 3);  fchunk(acc, rvA, &wS[2 * 80 + 2 * 16]);
    load_window(rvA, cb2, 4);  fchunk(acc, rvB, &wS[2 * 80 + 3 * 16]);
                               fchunk(acc, rvA, &wS[2 * 80 + 4 * 16]);

    const int col = xb + tid;
    #pragma unroll
    for (int co = 0; co < 3; ++co) {
        float2* obP = OUTP ? dstP + (((size_t)(pair * 3 + co)) << 20) + col : nullptr;
        float*  obA = OUTP ? nullptr : dstN + (((size_t)(pair * 3 + co)) << 20) + col;
        float*  obB = OUTP ? nullptr : obA + (((size_t)24) << 20);
        #pragma unroll
        for (int p = 0; p < 8; ++p) {
            float2 y  = unpack2(acc[co][p]);
            float2 xp = smx[co][p + 2][tid + 2];
            float a = __saturatef(fmaf(fmaxf(y.x, 0.0f), 0.1f, xp.x));
            float b = __saturatef(fmaf(fmaxf(y.y, 0.0f), 0.1f, xp.y));
            if (OUTP) {
                obP[(rb + p) << 10] = make_float2(a, b);
            } else {
                obA[(rb + p) << 10] = a;
                obB[(rb + p) << 10] = b;
            }
        }
    }
}

// ===========================================================================
// Steps 1..8: two y-adjacent 8-row tiles per block. Main buffer (12 rows) via
// LDG/STS; aux buffer (8 new rows for tile 2) via cp.async overlapped with
// tile-1 compute. Hot loop identical FFMA2 structure; tile-2 window split is
// compile-time (main[8..11] + aux[0..7]).
// SMEM (dynamic): smx 3x12x132 f2 (38016) | aux 3x8x132 f2 (25344) | wS (1920)
// ===========================================================================
#define SMX2_B  38016
#define AUX2_B  25344
#define DSM2_B  (SMX2_B + AUX2_B + 1920)

__global__ void __launch_bounds__(128, 3) ca_step2(const float2* __restrict__ srcP,
                                                   float2*       __restrict__ dstP)
{
    extern __shared__ __align__(16) char dsm[];
    float2 (*smx)[12][132] = reinterpret_cast<float2(*)[12][132]>(dsm);
    float2 (*aux)[8][132]  = reinterpret_cast<float2(*)[8][132]>(dsm + SMX2_B);
    ull*    wS             = reinterpret_cast<ull*>(dsm + SMX2_B + AUX2_B);

    const int tid  = threadIdx.x;
    const int xb   = blockIdx.x * 128;
    const int rb   = blockIdx.y * 16;      // 16 output rows per block
    const int pair = blockIdx.z;

    if (tid < 120) {
        wS[tid]       = g_wpack[tid];
        wS[tid + 120] = g_wpack[tid + 120];
    }

    // ---- aux cp.async FIRST (image rows rb+10..rb+17), overlaps everything ----
    {
        // interior: 3ch x 8 rows x 64 16B-chunks = 1536 = 12/thread, all shifts
        #pragma unroll
        for (int k = 0; k < 12; ++k) {
            int i   = k * 128 + tid;
            int ch  = i >> 9;
            int rem = i & 511;
            int r   = rem >> 6;
            int c2  = rem & 63;
            const float2* sp = srcP + (((size_t)(pair * 3 + ch)) << 20)
                             + (((rb + 10 + r) & 1023) << 10) + xb + 2 * c2;
            cp16(&aux[ch][r][2 + 2 * c2], sp);
        }
        // halo: 3ch x 8 rows x 2 sides = 48
        if (tid < 48) {
            int ch   = tid >> 4;
            int rem  = tid & 15;
            int r    = rem >> 1;
            int side = rem & 1;
            int gcol = side ? ((xb + 128) & 1023) : ((xb - 2) & 1023);
            int sidx = side ? 130 : 0;
            const float2* sp = srcP + (((size_t)(pair * 3 + ch)) << 20)
                             + (((rb + 10 + r) & 1023) << 10) + gcol;
            cp16(&aux[ch][r][sidx], sp);
        }
        cp_commit();
    }

    // ---- main buffer loader (image rows rb-2..rb+9), R12-proven path ----
    #pragma unroll
    for (int ch = 0; ch < 3; ++ch) {
        const float2* pbase = srcP + (((size_t)(pair * 3 + ch)) << 20);
        #pragma unroll
        for (int k = 0; k < 6; ++k) {
            int j   = k * 128 + tid;
            int row = j >> 6;
            int c2  = j & 63;
            const float4* sp = reinterpret_cast<const float4*>(
                pbase + (((rb + row - 2) & 1023) << 10) + xb + 2 * c2);
            *reinterpret_cast<float4*>(&smx[ch][row][2 + 2 * c2]) = *sp;
        }
    }
    if (tid < 72) {
        int ch   = tid / 24;
        int rem  = tid - ch * 24;
        int row  = rem >> 1;
        int side = rem & 1;
        int gcol = side ? ((xb + 128) & 1023) : ((xb - 2) & 1023);
        int sidx = side ? 130 : 0;
        const float2* pbase = srcP + (((size_t)(pair * 3 + ch)) << 20);
        const float4* sp = reinterpret_cast<const float4*>(
            pbase + (((rb + row - 2) & 1023) << 10) + gcol);
        *reinterpret_cast<float4*>(&smx[ch][row][sidx]) = *sp;
    }
    __syncthreads();

    const int col = xb + tid;

    // ================= tile 1: output rows rb..rb+7 =================
    {
        ull acc[3][8];
        #pragma unroll
        for (int co = 0; co < 3; ++co)
            #pragma unroll
            for (int p = 0; p < 8; ++p)
                acc[co][p] = 0ull;

        const float2* cb0 = &smx[0][0][tid];
        const float2* cb1 = &smx[1][0][tid];
        const float2* cb2 = &smx[2][0][tid];

        ull rvA[12], rvB[12];
        load_window(rvA, cb0, 0);
        load_window(rvB, cb0, 1);  fchunk(acc, rvA, &wS[0 * 80 + 0 * 16]);
        load_window(rvA, cb0, 2);  fchunk(acc, rvB, &wS[0 * 80 + 1 * 16]);
        load_window(rvB, cb0, 3);  fchunk(acc, rvA, &wS[0 * 80 + 2 * 16]);
        load_window(rvA, cb0, 4);  fchunk(acc, rvB, &wS[0 * 80 + 3 * 16]);
        load_window(rvB, cb1, 0);  fchunk(acc, rvA, &wS[0 * 80 + 4 * 16]);
        load_window(rvA, cb1, 1);  fchunk(acc, rvB, &wS[1 * 80 + 0 * 16]);
        load_window(rvB, cb1, 2);  fchunk(acc, rvA, &wS[1 * 80 + 1 * 16]);
        load_window(rvA, cb1, 3);  fchunk(acc, rvB, &wS[1 * 80 + 2 * 16]);
        load_window(rvB, cb1, 4);  fchunk(acc, rvA, &wS[1 * 80 + 3 * 16]);
        load_window(rvA, cb2, 0);  fchunk(acc, rvB, &wS[1 * 80 + 4 * 16]);
        load_window(rvB, cb2, 1);  fchunk(acc, rvA, &wS[2 * 80 + 0 * 16]);
        load_window(rvA, cb2, 2);  fchunk(acc, rvB, &wS[2 * 80 + 1 * 16]);
        load_window(rvB, cb2, 3);  fchunk(acc, rvA, &wS[2 * 80 + 2 * 16]);
        load_window(rvA, cb2, 4);  fchunk(acc, rvB, &wS[2 * 80 + 3 * 16]);
                                   fchunk(acc, rvA, &wS[2 * 80 + 4 * 16]);

        #pragma unroll
        for (int co = 0; co < 3; ++co) {
            float2* obP = dstP + (((size_t)(pair * 3 + co)) << 20) + col;
            #pragma unroll
            for (int p = 0; p < 8; ++p) {
                float2 y  = unpack2(acc[co][p]);
                float2 xp = smx[co][p + 2][tid + 2];
                obP[(rb + p) << 10] = make_float2(
                    __saturatef(fmaf(fmaxf(y.x, 0.0f), 0.1f, xp.x)),
                    __saturatef(fmaf(fmaxf(y.y, 0.0f), 0.1f, xp.y)));
            }
        }
    }

    // aux must be complete & visible before tile 2
    cp_wait_all();
    __syncthreads();

    // ================= tile 2: output rows rb+8..rb+15 =================
    {
        ull acc[3][8];
        #pragma unroll
        for (int co = 0; co < 3; ++co)
            #pragma unroll
            for (int p = 0; p < 8; ++p)
                acc[co][p] = 0ull;

        const float2* cM0 = &smx[0][8][tid];
        const float2* cM1 = &smx[1][8][tid];
        const float2* cM2 = &smx[2][8][tid];
        const float2* cA0 = &aux[0][0][tid];
        const float2* cA1 = &aux[1][0][tid];
        const float2* cA2 = &aux[2][0][tid];

        ull rvA[12], rvB[12];
        load_window2(rvA, cM0, cA0, 0);
        load_window2(rvB, cM0, cA0, 1);  fchunk(acc, rvA, &wS[0 * 80 + 0 * 16]);
        load_window2(rvA, cM0, cA0, 2);  fchunk(acc, rvB, &wS[0 * 80 + 1 * 16]);
        load_window2(rvB, cM0, cA0, 3);  fchunk(acc, rvA, &wS[0 * 80 + 2 * 16]);
        load_window2(rvA, cM0, cA0, 4);  fchunk(acc, rvB, &wS[0 * 80 + 3 * 16]);
        load_window2(rvB, cM1, cA1, 0);  fchunk(acc, rvA, &wS[0 * 80 + 4 * 16]);
        load_window2(rvA, cM1, cA1, 1);  fchunk(acc, rvB, &wS[1 * 80 + 0 * 16]);
        load_window2(rvB, cM1, cA1, 2);  fchunk(acc, rvA, &wS[1 * 80 + 1 * 16]);
        load_window2(rvA, cM1, cA1, 3);  fchunk(acc, rvB, &wS[1 * 80 + 2 * 16]);
        load_window2(rvB, cM1, cA1, 4);  fchunk(acc, rvA, &wS[1 * 80 + 3 * 16]);
        load_window2(rvA, cM2, cA2, 0);  fchunk(acc, rvB, &wS[1 * 80 + 4 * 16]);
        load_window2(rvB, cM2, cA2, 1);  fchunk(acc, rvA, &wS[2 * 80 + 0 * 16]);
        load_window2(rvA, cM2, cA2, 2);  fchunk(acc, rvB, &wS[2 * 80 + 1 * 16]);
        load_window2(rvB, cM2, cA2, 3);  fchunk(acc, rvA, &wS[2 * 80 + 2 * 16]);
        load_window2(rvA, cM2, cA2, 4);  fchunk(acc, rvB, &wS[2 * 80 + 3 * 16]);
                                         fchunk(acc, rvA, &wS[2 * 80 + 4 * 16]);

        #pragma unroll
        for (int co = 0; co < 3; ++co) {
            float2* obP = dstP + (((size_t)(pair * 3 + co)) << 20) + col;
            #pragma unroll
            for (int p = 0; p < 8; ++p) {
                float2 y = unpack2(acc[co][p]);
                // input at output row rb+8+p: p<2 -> main[10+p], else aux[p-2]
                float2 xp = (p < 2) ? smx[co][10 + p][tid + 2]
                                    : aux[co][p - 2][tid + 2];
                obP[(rb + 8 + p) << 10] = make_float2(
                    __saturatef(fmaf(fmaxf(y.x, 0.0f), 0.1f, xp.x)),
                    __saturatef(fmaf(fmaxf(y.y, 0.0f), 0.1f, xp.y)));
            }
        }
    }
}

extern "C" void kernel_launch(void* const* d_in, const int* in_sizes, int n_in,
                              void* d_out, int out_size)
{
    const float* x = (const float*)d_in[0];
    const float* W = (const float*)d_in[1];
    float* out = (float*)d_out;

    float2 *p0 = nullptr, *p1 = nullptr;
    cudaGetSymbolAddress((void**)&p0, g_p0);
    cudaGetSymbolAddress((void**)&p1, g_p1);

    cudaFuncSetAttribute(ca_step2, cudaFuncAttributeMaxDynamicSharedMemorySize,
                         DSM2_B);

    pack_w<<<1, 256>>>(W);

    dim3 block(128);
    dim3 grid1(8, 128, 8);   // single-tile kernel (steps 0, 9)
    dim3 grid2(8, 64, 8);    // two-tile kernel  (steps 1..8)

    // s0: normal x -> paired p0
    ca_step<0, 1><<<grid1, block>>>(x, nullptr, nullptr, p0);
    // s1..s8: paired ping-pong, two tiles per block with cp.async overlap
    float2* pin = p0;
    float2* pout = p1;
    for (int s = 1; s <= 8; ++s) {
        ca_step2<<<grid2, block, DSM2_B>>>(pin, pout);
        float2* t = pin; pin = pout; pout = t;
    }
    // s9: paired -> normal d_out
    ca_step<1, 0><<<grid1, block>>>(nullptr, pin, out, nullptr);
}

// round 16
// speedup vs baseline: 1.1480x; 1.1480x over previous
#include <cuda_runtime.h>

typedef unsigned long long ull;

// image-paired ping-pong buffers: P[pair][ch][row][col] = float2(x[img p], x[img p+8])
// pair p in 0..7.  ~201 MB each (allocation-free rule: __device__ globals)
__device__ float2 g_p0[8u * 3u * 1024u * 1024u];
__device__ float2 g_p1[8u * 3u * 1024u * 1024u];
// pre-packed (w,w) f32x2 weights, layout [ci][kx][s=co*5+ky] padded to 16
__device__ ull    g_wpack[240];

__device__ __forceinline__ ull pack2(float lo, float hi) {
    ull r;
    asm("mov.b64 %0, {%1, %2};" : "=l"(r) : "f"(lo), "f"(hi));
    return r;
}
__device__ __forceinline__ float2 unpack2(ull v) {
    float2 r;
    asm("mov.b64 {%0, %1}, %2;" : "=f"(r.x), "=f"(r.y) : "l"(v));
    return r;
}
// packed fp32x2 FMA (FFMA2) -- only reachable via PTX fma.rn.f32x2
__device__ __forceinline__ void fma2(ull& d, ull a, ull b) {
    asm("fma.rn.f32x2 %0, %1, %2, %0;" : "+l"(d) : "l"(a), "l"(b));
}

// prep: broadcast-pack weights once; W is OIHW [co][ci][ky][kx] = [3][3][5][5]
__global__ void pack_w(const float* __restrict__ W) {
    int i = threadIdx.x;
    if (i >= 240) return;
    int ci = i / 80;
    int r  = i - ci * 80;
    int kx = r / 16;
    int s  = r - kx * 16;
    float w = 0.0f;
    if (s < 15) {
        int co = s / 5;
        int ky = s - co * 5;
        w = W[co * 75 + ci * 25 + ky * 5 + kx];
    }
    g_wpack[i] = pack2(w, w);
}

// 8 packed FMAs: one weight pair against window rows base..base+7
__device__ __forceinline__ void fma8(ull* accrow, const ull* base, ull w) {
    #pragma unroll
    for (int p = 0; p < 8; ++p)
        fma2(accrow[p], base[p], w);
}
// 12 conflict-free LDS.64: one column window, all window rows
__device__ __forceinline__ void load_window(ull* rv, const float2* colbase, int kx) {
    #pragma unroll
    for (int p = 0; p < 12; ++p)
        rv[p] = *reinterpret_cast<const ull*>(colbase + p * 132 + kx);
}
// one (ci,kx) chunk: 8 weight LDS.128 pairs + 120 FFMA2 (R5/R6-proven order)
__device__ __forceinline__ void fchunk(ull (*acc)[8], const ull* rv, const ull* wrow) {
    const ulonglong2* wv = reinterpret_cast<const ulonglong2*>(wrow);
    #pragma unroll
    for (int j = 0; j < 7; ++j) {
        ulonglong2 q = wv[j];
        const int s0 = 2 * j;
        const int s1 = 2 * j + 1;
        fma8(acc[s0 / 5], rv + (s0 % 5), q.x);
        fma8(acc[s1 / 5], rv + (s1 % 5), q.y);
    }
    fma8(acc[2], rv + 4, wrow[14]);   // s=14 -> co=2, ky=4
}

// Block: 128 threads. Tile: 128 cols x 8 rows x 3 ch x 2 images (paired).
// smx[ch][r][xi] = float2(imgA, imgB) at (row rb+r-2, col xb+xi-2).
// Output row rb+p with tap ky reads window row p+ky at col tid+kx.
// Pairing axis is the batch, so paired gmem (steps 1..8) loads/stores with
// ZERO shuffling.  4 blocks/SM; 2-deep rvA/rvB software pipeline in-warp.
template <int INP, int OUTP>
__global__ void __launch_bounds__(128, 4) ca_step(const float*  __restrict__ srcN,
                                                  const float2* __restrict__ srcP,
                                                  float*        __restrict__ dstN,
                                                  float2*       __restrict__ dstP)
{
    __shared__ __align__(16) float2 smx[3][12][132];
    __shared__ __align__(16) ull    wS[240];

    const int tid  = threadIdx.x;
    const int xb   = blockIdx.x * 128;
    const int rb   = blockIdx.y * 8;
    const int pair = blockIdx.z;          // images (pair, pair+8)

    // ---- weights -> smem ----
    if (tid < 120) {
        wS[tid]       = g_wpack[tid];
        wS[tid + 120] = g_wpack[tid + 120];
    }

    if (INP) {
        // ===== paired loader: pure contiguous 16B copies, no shuffle =====
        #pragma unroll
        for (int ch = 0; ch < 3; ++ch) {
            const float2* pbase = srcP + (((size_t)(pair * 3 + ch)) << 20);
            #pragma unroll
            for (int k = 0; k < 6; ++k) {
                int j   = k * 128 + tid;       // 0..767
                int row = j >> 6;              // 0..11
                int c2  = j & 63;              // 16B chunk (2 cols)
                const float4* sp = reinterpret_cast<const float4*>(
                    pbase + (((rb + row - 2) & 1023) << 10) + xb + 2 * c2);
                *reinterpret_cast<float4*>(&smx[ch][row][2 + 2 * c2]) = *sp;
            }
        }
        // halo: 3ch x 12 rows x 2 sides; wrapped col pairs are gmem-contiguous
        if (tid < 72) {
            int ch   = tid / 24;
            int rem  = tid - ch * 24;
            int row  = rem >> 1;
            int side = rem & 1;
            int gcol = side ? ((xb + 128) & 1023) : ((xb - 2) & 1023);
            int sidx = side ? 130 : 0;
            const float2* pbase = srcP + (((size_t)(pair * 3 + ch)) << 20);
            const float4* sp = reinterpret_cast<const float4*>(
                pbase + (((rb + row - 2) & 1023) << 10) + gcol);
            *reinterpret_cast<float4*>(&smx[ch][row][sidx]) = *sp;
        }
    } else {
        // ===== normal loader (step 0): interleave imgs (pair, pair+8) =====
        #pragma unroll
        for (int ch = 0; ch < 3; ++ch) {
            const float* baseA = srcN + (((size_t)(pair * 3 + ch)) << 20);
            const float* baseB = baseA + (((size_t)24) << 20);
            #pragma unroll
            for (int k = 0; k < 3; ++k) {
                int j   = k * 128 + tid;       // 0..383
                int row = j >> 5;              // 0..11
                int g   = j & 31;              // float4 group (4 cols)
                int off = (((rb + row - 2) & 1023) << 10) + xb + 4 * g;
                float4 a = *reinterpret_cast<const float4*>(baseA + off);
                float4 b = *reinterpret_cast<const float4*>(baseB + off);
                float4* s = reinterpret_cast<float4*>(&smx[ch][row][2 + 4 * g]);
                s[0] = make_float4(a.x, b.x, a.y, b.y);
                s[1] = make_float4(a.z, b.z, a.w, b.w);
            }
        }
        if (tid < 72) {
            int ch   = tid / 24;
            int rem  = tid - ch * 24;
            int row  = rem >> 1;
            int side = rem & 1;
            int gcol = side ? ((xb + 128) & 1023) : ((xb - 2) & 1023);
            int sidx = side ? 130 : 0;
            const float* baseA = srcN + (((size_t)(pair * 3 + ch)) << 20);
            const float* baseB = baseA + (((size_t)24) << 20);
            int off = (((rb + row - 2) & 1023) << 10) + gcol;
            float2 a = *reinterpret_cast<const float2*>(baseA + off);
            float2 b = *reinterpret_cast<const float2*>(baseB + off);
            *reinterpret_cast<float4*>(&smx[ch][row][sidx]) =
                make_float4(a.x, b.x, a.y, b.y);
        }
    }
    __syncthreads();

    // ---- conv accumulation: 3 out-channels x 8 rows, batch-packed f32x2 ----
    ull acc[3][8];
    #pragma unroll
    for (int co = 0; co < 3; ++co)
        #pragma unroll
        for (int p = 0; p < 8; ++p)
            acc[co][p] = 0ull;

    const float2* cb0 = &smx[0][0][tid];
    const float2* cb1 = &smx[1][0][tid];
    const float2* cb2 = &smx[2][0][tid];

    ull rvA[12], rvB[12];
    // 15 chunks (ci,kx), 2-deep pipeline (R6/R12-proven, byte-identical)
    load_window(rvA, cb0, 0);
    load_window(rvB, cb0, 1);  fchunk(acc, rvA, &wS[0 * 80 + 0 * 16]);
    load_window(rvA, cb0, 2);  fchunk(acc, rvB, &wS[0 * 80 + 1 * 16]);
    load_window(rvB, cb0, 3);  fchunk(acc, rvA, &wS[0 * 80 + 2 * 16]);
    load_window(rvA, cb0, 4);  fchunk(acc, rvB, &wS[0 * 80 + 3 * 16]);
    load_window(rvB, cb1, 0);  fchunk(acc, rvA, &wS[0 * 80 + 4 * 16]);
    load_window(rvA, cb1, 1);  fchunk(acc, rvB, &wS[1 * 80 + 0 * 16]);
    load_window(rvB, cb1, 2);  fchunk(acc, rvA, &wS[1 * 80 + 1 * 16]);
    load_window(rvA, cb1, 3);  fchunk(acc, rvB, &wS[1 * 80 + 2 * 16]);
    load_window(rvB, cb1, 4);  fchunk(acc, rvA, &wS[1 * 80 + 3 * 16]);
    load_window(rvA, cb2, 0);  fchunk(acc, rvB, &wS[1 * 80 + 4 * 16]);
    load_window(rvB, cb2, 1);  fchunk(acc, rvA, &wS[2 * 80 + 0 * 16]);
    load_window(rvA, cb2, 2);  fchunk(acc, rvB, &wS[2 * 80 + 1 * 16]);
    load_window(rvB, cb2, 3);  fchunk(acc, rvA, &wS[2 * 80 + 2 * 16]);
    load_window(rvA, cb2, 4);  fchunk(acc, rvB, &wS[2 * 80 + 3 * 16]);
                               fchunk(acc, rvA, &wS[2 * 80 + 4 * 16]);

    // ---- epilogue: out = clip(x + 0.1*relu(y), 0, 1) ----
    const int col = xb + tid;
    #pragma unroll
    for (int co = 0; co < 3; ++co) {
        float2* obP = OUTP ? dstP + (((size_t)(pair * 3 + co)) << 20) + col : nullptr;
        float*  obA = OUTP ? nullptr : dstN + (((size_t)(pair * 3 + co)) << 20) + col;
        float*  obB = OUTP ? nullptr : obA + (((size_t)24) << 20);
        #pragma unroll
        for (int p = 0; p < 8; ++p) {
            float2 y  = unpack2(acc[co][p]);
            float2 xp = smx[co][p + 2][tid + 2];   // input (imgA, imgB) at out loc
            float a = __saturatef(fmaf(fmaxf(y.x, 0.0f), 0.1f, xp.x));
            float b = __saturatef(fmaf(fmaxf(y.y, 0.0f), 0.1f, xp.y));
            if (OUTP) {
                obP[(rb + p) << 10] = make_float2(a, b);   // coalesced STG.64
            } else {
                obA[(rb + p) << 10] = a;
                obB[(rb + p) << 10] = b;
            }
        }
    }
}

extern "C" void kernel_launch(void* const* d_in, const int* in_sizes, int n_in,
                              void* d_out, int out_size)
{
    const float* x = (const float*)d_in[0];
    const float* W = (const float*)d_in[1];
    float* out = (float*)d_out;

    float2 *p0 = nullptr, *p1 = nullptr;
    cudaGetSymbolAddress((void**)&p0, g_p0);
    cudaGetSymbolAddress((void**)&p1, g_p1);

    pack_w<<<1, 256>>>(W);

    dim3 grid(8, 128, 8);   // 1024/128 cols, 1024/8 rows, 8 image pairs
    dim3 block(128);

    // s0: normal x -> paired p0
    ca_step<0, 1><<<grid, block>>>(x, nullptr, nullptr, p0);
    // s1..s8: paired ping-pong (zero-shuffle loads/stores)
    float2* pin = p0;
    float2* pout = p1;
    for (int s = 1; s <= 8; ++s) {
        ca_step<1, 1><<<grid, block>>>(nullptr, pin, nullptr, pout);
        float2* t = pin; pin = pout; pout = t;
    }
    // s9: paired -> normal d_out
    ca_step<1, 0><<<grid, block>>>(nullptr, pin, out, nullptr);
}